// round 12
// baseline (speedup 1.0000x reference)
#include <cuda_runtime.h>
#include <math.h>

#define FEAT 64
#define KNN  16
#define K4   4
#define BB   4
#define NQ   8192
#define MP   8192
#define BNEPS 1e-5f
#define NSPLIT 4
#define SEG (MP / NSPLIT)    // 2048

// ---------------- device scratch (static, no allocation) ----------------
__device__ float  g_kd[BB * NQ * 64];       // per-query: 4 segments x 16 sorted distances
__device__ int    g_ki[BB * NQ * 64];       // matching indices
__device__ float4 g_A0[FEAT];               // folded conv0+bn0: (ax,ay,az, bias)
__device__ float2 g_A1p[FEAT * 32];         // folded conv1+bn1, paired: [c*32+l] = (A1[l][c], A1[l+32][c])
__device__ float  g_c1[FEAT];               // folded conv1+bn1 bias

// ---------------- packed fp32x2 helpers ----------------
__device__ __forceinline__ unsigned long long fma2(unsigned long long a,
                                                   unsigned long long b,
                                                   unsigned long long c) {
    unsigned long long d;
    asm("fma.rn.f32x2 %0, %1, %2, %3;" : "=l"(d) : "l"(a), "l"(b), "l"(c));
    return d;
}
__device__ __forceinline__ unsigned long long pk2(float lo, float hi) {
    unsigned long long r;
    asm("mov.b64 %0, {%1, %2};" : "=l"(r) : "f"(lo), "f"(hi));
    return r;
}
__device__ __forceinline__ float2 upk(unsigned long long v) {
    float2 r;
    asm("mov.b64 {%0, %1}, %2;" : "=f"(r.x), "=f"(r.y) : "l"(v));
    return r;
}

// ---------------- prep: fold BN into conv weights ----------------
__global__ void prep_kernel(const float* __restrict__ w0, const float* __restrict__ b0,
                            const float* __restrict__ g0, const float* __restrict__ be0,
                            const float* __restrict__ m0, const float* __restrict__ v0,
                            const float* __restrict__ w1, const float* __restrict__ b1,
                            const float* __restrict__ g1, const float* __restrict__ be1,
                            const float* __restrict__ m1, const float* __restrict__ v1) {
    int t = threadIdx.x;
    if (t < FEAT) {
        float inv0 = g0[t] / sqrtf(v0[t] + BNEPS);
        g_A0[t] = make_float4(w0[t * 3 + 0] * inv0,
                              w0[t * 3 + 1] * inv0,
                              w0[t * 3 + 2] * inv0,
                              (b0[t] - m0[t]) * inv0 + be0[t]);
        float inv1 = g1[t] / sqrtf(v1[t] + BNEPS);
        g_c1[t] = (b1[t] - m1[t]) * inv1 + be1[t];
    }
    for (int e = t; e < FEAT * 32; e += blockDim.x) {
        int c = e >> 5, l = e & 31;
        float invA = g1[l]      / sqrtf(v1[l]      + BNEPS);
        float invB = g1[l + 32] / sqrtf(v1[l + 32] + BNEPS);
        g_A1p[e] = make_float2(w1[l * FEAT + c] * invA,
                               w1[(l + 32) * FEAT + c] * invB);
    }
}

// ---------------- phase 1: brute-force KNN over an M-segment ----------------
// Packed-pair bitmask filter (conservative surrogate, slack 1e-3 >> ~1e-5
// rounding skew); drain walks set bits and recomputes the reference's exact
// fp32 arithmetic:
//   q2 = (qx*qx + qy*qy) + qz*qz ; o2 likewise (plain rn mul/add)
//   cross = fma(qz,oz, fma(qy,oy, rn(qx*ox)))
//   d2 = (q2 + o2) - (2*cross)
#define T1   128
#define TILE 1024
#define PCH  8           // pairs per chunk = 16 candidates (small: keep live ranges tight)

__global__ __launch_bounds__(T1, 7) void knn_kernel(const float* __restrict__ op,
                                                    const float* __restrict__ qp) {
    __shared__ ulonglong2 shXY[TILE / 2];   // {x-pair, y-pair}  8 KB
    __shared__ ulonglong2 shZW[TILE / 2];   // {z-pair, (-o2)-pair}  8 KB

    const int tid  = threadIdx.x;
    const int b    = blockIdx.y;
    const int segi = blockIdx.z;
    const int n    = blockIdx.x * T1 + tid;
    const float* opb = op + (size_t)b * 3 * MP;

    const float qx = qp[(size_t)b * 3 * NQ + n];
    const float qy = qp[(size_t)b * 3 * NQ + NQ + n];
    const float qz = qp[(size_t)b * 3 * NQ + 2 * NQ + n];
    const float q2 = __fadd_rn(__fadd_rn(__fmul_rn(qx, qx), __fmul_rn(qy, qy)),
                               __fmul_rn(qz, qz));
    const unsigned long long tqx2 = pk2(qx + qx, qx + qx);
    const unsigned long long tqy2 = pk2(qy + qy, qy + qy);
    const unsigned long long tqz2 = pk2(qz + qz, qz + qz);

    float best[KNN];   // sorted ascending
    int   bidx[KNN];
#pragma unroll
    for (int i = 0; i < KNN; i++) { best[i] = 3.4e38f; bidx[i] = 0; }
    float c0 = -3.4e38f;   // pass iff surrogate t > c0 (saturated while sentinel)

    const int base0 = segi * SEG;
    for (int base = base0; base < base0 + SEG; base += TILE) {
        __syncthreads();
        // ---- load tile in packed-pair layout ----
        for (int i = tid; i < TILE / 2; i += T1) {
            int g = base + 2 * i;
            float x0 = opb[g],          x1 = opb[g + 1];
            float y0 = opb[MP + g],     y1 = opb[MP + g + 1];
            float z0 = opb[2 * MP + g], z1 = opb[2 * MP + g + 1];
            float o20 = __fadd_rn(__fadd_rn(__fmul_rn(x0, x0), __fmul_rn(y0, y0)),
                                  __fmul_rn(z0, z0));
            float o21 = __fadd_rn(__fadd_rn(__fmul_rn(x1, x1), __fmul_rn(y1, y1)),
                                  __fmul_rn(z1, z1));
            shXY[i] = make_ulonglong2(pk2(x0, x1), pk2(y0, y1));
            shZW[i] = make_ulonglong2(pk2(z0, z1), pk2(-o20, -o21));
        }
        __syncthreads();

        for (int cp = 0; cp < TILE / 2; cp += PCH) {
            unsigned mask = 0u;
            // ---- packed bitmask filter ----
#pragma unroll
            for (int pp = 0; pp < PCH; pp++) {
                ulonglong2 xy = shXY[cp + pp];
                ulonglong2 zw = shZW[cp + pp];
                unsigned long long t2 =
                    fma2(tqz2, zw.x, fma2(tqy2, xy.y, fma2(tqx2, xy.x, zw.y)));
                float2 t = upk(t2);
                if (fmaxf(t.x, t.y) > c0) mask |= (1u << pp);
            }
            // ---- drain flagged pairs (divergent, rare) ----
            while (mask) {
                int pp = __ffs(mask) - 1;
                mask &= mask - 1;
                ulonglong2 xy = shXY[cp + pp];
                ulonglong2 zw = shZW[cp + pp];
                float2 xs = upk(xy.x), ys = upk(xy.y), zs = upk(zw.x), ws = upk(zw.y);
#pragma unroll
                for (int e = 0; e < 2; e++) {
                    float ox = e ? xs.y : xs.x;
                    float oy = e ? ys.y : ys.x;
                    float oz = e ? zs.y : zs.x;
                    float o2 = -(e ? ws.y : ws.x);
                    float cross = fmaf(qz, oz, fmaf(qy, oy, __fmul_rn(qx, ox)));
                    float d2 = __fsub_rn(__fadd_rn(q2, o2), __fmul_rn(2.0f, cross));
                    if (d2 < best[KNN - 1]) {
                        int m = base + 2 * (cp + pp) + e;
                        bool pr[KNN];
#pragma unroll
                        for (int i = 0; i < KNN; i++) pr[i] = best[i] > d2;
#pragma unroll
                        for (int i = KNN - 1; i >= 1; i--)
                            if (pr[i - 1]) { best[i] = best[i - 1]; bidx[i] = bidx[i - 1]; }
#pragma unroll
                        for (int i = 0; i < KNN; i++)
                            if (pr[i] && (i == 0 || !pr[i - 1])) { best[i] = d2; bidx[i] = m; }
                        c0 = __fsub_rn(__fsub_rn(q2, best[KNN - 1]), 1e-3f);
                    }
                }
            }
        }
    }

    float* dk = g_kd + ((size_t)b * NQ + n) * 64 + segi * KNN;
    int*   di = g_ki + ((size_t)b * NQ + n) * 64 + segi * KNN;
#pragma unroll
    for (int i = 0; i < KNN; i++) { dk[i] = best[i]; di[i] = bidx[i]; }
}

// ---------------- phase 2: merge 4 lists + fused MLP + gather + blend ----------------
// 512 threads = 16 warps, one query per warp.
#define QPB 16

// bitonic merge of a 32-lane bitonic sequence, ascending, ties by lower index
__device__ __forceinline__ void bitonic32(float& d, int& id, int lane) {
#pragma unroll
    for (int j = 16; j >= 1; j >>= 1) {
        float od = __shfl_xor_sync(0xffffffffu, d, j);
        int   oi = __shfl_xor_sync(0xffffffffu, id, j);
        bool mineSmall = (d < od) || (d == od && id < oi);
        bool lower = !(lane & j);
        if (lower != mineSmall) { d = od; id = oi; }
    }
}

// combine two sorted-32s (top16 in lanes 0..15 of each) into one sorted-32
__device__ __forceinline__ void mergeTop(float& dA, int& iA, float dB, int iB, int lane) {
    float dBr = __shfl_sync(0xffffffffu, dB, 31 - lane);
    int   iBr = __shfl_sync(0xffffffffu, iB, 31 - lane);
    if (lane >= 16) { dA = dBr; iA = iBr; }
    bitonic32(dA, iA, lane);
}

__global__ __launch_bounds__(512) void feat_kernel(const float* __restrict__ op,
                                                   const float* __restrict__ qp,
                                                   const float* __restrict__ lf,
                                                   const float* __restrict__ w2,
                                                   const float* __restrict__ b2,
                                                   float* __restrict__ out) {
    __shared__ float2 shA1[FEAT * 32];       // 16 KB
    __shared__ float4 shF0[QPB][FEAT];       // 16 KB
    __shared__ float  shOut[FEAT][QPB + 2];  // padded stride

    const int tid  = threadIdx.x;
    const int warp = tid >> 5;
    const int lane = tid & 31;

    for (int i = tid; i < FEAT * 32; i += 512) shA1[i] = g_A1p[i];
    __syncthreads();

    const int b = blockIdx.y;
    const int n = blockIdx.x * QPB + warp;

    // ---- merge four sorted 16-lists into global top-16 ----
    const float* dk = g_kd + ((size_t)b * NQ + n) * 64;
    const int*   di = g_ki + ((size_t)b * NQ + n) * 64;

    int sA = (lane < 16) ? lane : (16 + 31 - lane);         // lists 0,1 -> bitonic
    float dA = dk[sA];  int iA = di[sA];
    bitonic32(dA, iA, lane);                                // sorted 32; top16 in lanes 0..15

    int sB = (lane < 16) ? (32 + lane) : (48 + 31 - lane);  // lists 2,3 -> bitonic
    float dB = dk[sB];  int iB = di[sB];
    bitonic32(dB, iB, lane);

    mergeTop(dA, iA, dB, iB, lane);
    // lanes 0..15 hold the global top-16 ascending (ties: lower index first)
    const int myidx = iA;

    const float qx = qp[(size_t)b * 3 * NQ + n];
    const float qy = qp[(size_t)b * 3 * NQ + NQ + n];
    const float qz = qp[(size_t)b * 3 * NQ + 2 * NQ + n];

    float rx = 0.f, ry = 0.f, rz = 0.f;
    if (lane < KNN) {
        const float* opb = op + (size_t)b * 3 * MP;
        rx = opb[myidx] - qx;
        ry = opb[MP + myidx] - qy;
        rz = opb[2 * MP + myidx] - qz;
    }

    const int f0 = lane, f1 = lane + 32;
    const float4 a0 = g_A0[f0];
    const float4 a1 = g_A0[f1];

    float gmax0 = 0.f, gmax1 = 0.f;   // relu outputs >= 0
#pragma unroll
    for (int k = 0; k < KNN; k++) {
        float ox = __shfl_sync(0xffffffffu, rx, k);
        float oy = __shfl_sync(0xffffffffu, ry, k);
        float oz = __shfl_sync(0xffffffffu, rz, k);
        float v0 = fmaxf(0.f, fmaf(a0.x, ox, fmaf(a0.y, oy, fmaf(a0.z, oz, a0.w))));
        float v1 = fmaxf(0.f, fmaf(a1.x, ox, fmaf(a1.y, oy, fmaf(a1.z, oz, a1.w))));
        gmax0 = fmaxf(gmax0, v0);
        gmax1 = fmaxf(gmax1, v1);
        if (k < K4) {
            ((float*)&shF0[warp][f0])[k] = v0;
            ((float*)&shF0[warp][f1])[k] = v1;
        }
    }
    __syncwarp();

    float sg = fmaf(w2[FEAT + f0], gmax0, w2[FEAT + f1] * gmax1);

    float a00 = 0.f, a01 = 0.f, a02 = 0.f, a03 = 0.f;
    float a10 = 0.f, a11 = 0.f, a12 = 0.f, a13 = 0.f;
#pragma unroll 8
    for (int c = 0; c < FEAT; c++) {
        float4 x = shF0[warp][c];            // broadcast LDS.128
        float2 a = shA1[c * 32 + lane];      // conflict-free LDS.64
        a00 = fmaf(a.x, x.x, a00); a01 = fmaf(a.x, x.y, a01);
        a02 = fmaf(a.x, x.z, a02); a03 = fmaf(a.x, x.w, a03);
        a10 = fmaf(a.y, x.x, a10); a11 = fmaf(a.y, x.y, a11);
        a12 = fmaf(a.y, x.z, a12); a13 = fmaf(a.y, x.w, a13);
    }
    const float c1a = g_c1[f0], c1b = g_c1[f1];
    float rf0[K4] = { fmaxf(0.f, a00 + c1a), fmaxf(0.f, a01 + c1a),
                      fmaxf(0.f, a02 + c1a), fmaxf(0.f, a03 + c1a) };
    float rf1[K4] = { fmaxf(0.f, a10 + c1b), fmaxf(0.f, a11 + c1b),
                      fmaxf(0.f, a12 + c1b), fmaxf(0.f, a13 + c1b) };

    const float w2a0 = w2[f0], w2a1 = w2[f1];
    float s0 = fmaf(w2a0, rf0[0], w2a1 * rf1[0]);
    float s1 = fmaf(w2a0, rf0[1], w2a1 * rf1[1]);
    float s2 = fmaf(w2a0, rf0[2], w2a1 * rf1[2]);
    float s3 = fmaf(w2a0, rf0[3], w2a1 * rf1[3]);
#pragma unroll
    for (int off = 16; off; off >>= 1) {
        s0 += __shfl_xor_sync(0xffffffffu, s0, off);
        s1 += __shfl_xor_sync(0xffffffffu, s1, off);
        s2 += __shfl_xor_sync(0xffffffffu, s2, off);
        s3 += __shfl_xor_sync(0xffffffffu, s3, off);
        sg += __shfl_xor_sync(0xffffffffu, sg, off);
    }
    const float bb2 = b2[0];
    float wgt[K4];
    wgt[0] = 1.f / (1.f + expf(-(s0 + sg + bb2)));
    wgt[1] = 1.f / (1.f + expf(-(s1 + sg + bb2)));
    wgt[2] = 1.f / (1.f + expf(-(s2 + sg + bb2)));
    wgt[3] = 1.f / (1.f + expf(-(s3 + sg + bb2)));

    const float* lfb = lf + (size_t)b * FEAT * MP;
    float o0 = 0.f, o1 = 0.f;
#pragma unroll
    for (int j = 0; j < K4; j++) {
        int idj = __shfl_sync(0xffffffffu, myidx, j);
        float p0 = lfb[(size_t)f0 * MP + idj];
        float p1 = lfb[(size_t)f1 * MP + idj];
        o0 += rf0[j] + wgt[j] * (p0 - rf0[j]);
        o1 += rf1[j] + wgt[j] * (p1 - rf1[j]);
    }
    shOut[f0][warp] = o0;
    shOut[f1][warp] = o1;
    __syncthreads();

    // coalesced write: thread t -> feature t/8, n-offset (t%8)*2
    int f = tid >> 3, seg = tid & 7;
    int nbase = blockIdx.x * QPB;
    float2 v = make_float2(shOut[f][seg * 2], shOut[f][seg * 2 + 1]);
    *(float2*)&out[((size_t)b * FEAT + f) * NQ + nbase + seg * 2] = v;
}

// ---------------- launch ----------------
extern "C" void kernel_launch(void* const* d_in, const int* in_sizes, int n_in,
                              void* d_out, int out_size) {
    const float* original_pts = (const float*)d_in[0];
    const float* query_pts    = (const float*)d_in[1];
    const float* local_feat   = (const float*)d_in[2];
    const float* w0  = (const float*)d_in[3];
    const float* b0  = (const float*)d_in[4];
    const float* g0  = (const float*)d_in[5];
    const float* be0 = (const float*)d_in[6];
    const float* m0  = (const float*)d_in[7];
    const float* v0  = (const float*)d_in[8];
    const float* w1  = (const float*)d_in[9];
    const float* b1  = (const float*)d_in[10];
    const float* g1  = (const float*)d_in[11];
    const float* be1 = (const float*)d_in[12];
    const float* m1  = (const float*)d_in[13];
    const float* v1  = (const float*)d_in[14];
    const float* w2  = (const float*)d_in[15];
    const float* b2  = (const float*)d_in[16];
    float* out = (float*)d_out;

    // knn first so the profiler capture lands on the hot kernel.
    dim3 g1d(NQ / T1, BB, NSPLIT);
    knn_kernel<<<g1d, T1>>>(original_pts, query_pts);

    prep_kernel<<<1, 256>>>(w0, b0, g0, be0, m0, v0, w1, b1, g1, be1, m1, v1);

    dim3 g2d(NQ / QPB, BB);
    feat_kernel<<<g2d, 512>>>(original_pts, query_pts, local_feat, w2, b2, out);
}

// round 14
// speedup vs baseline: 1.2046x; 1.2046x over previous
#include <cuda_runtime.h>
#include <math.h>

#define FEAT 64
#define KNN  16
#define K4   4
#define BB   4
#define NQ   8192
#define MP   8192
#define BNEPS 1e-5f
#define NSPLIT 4
#define SEG (MP / NSPLIT)    // 2048

// ---------------- device scratch (static, no allocation) ----------------
__device__ float  g_kd[BB * NQ * 64];       // per-query: 4 segments x 16 sorted distances
__device__ int    g_ki[BB * NQ * 64];       // matching indices
__device__ float4 g_A0[FEAT];               // folded conv0+bn0: (ax,ay,az, bias)
__device__ float2 g_A1p[FEAT * 32];         // folded conv1+bn1, paired: [c*32+l] = (A1[l][c], A1[l+32][c])
__device__ float  g_c1[FEAT];               // folded conv1+bn1 bias

// ---------------- prep: fold BN into conv weights ----------------
__global__ void prep_kernel(const float* __restrict__ w0, const float* __restrict__ b0,
                            const float* __restrict__ g0, const float* __restrict__ be0,
                            const float* __restrict__ m0, const float* __restrict__ v0,
                            const float* __restrict__ w1, const float* __restrict__ b1,
                            const float* __restrict__ g1, const float* __restrict__ be1,
                            const float* __restrict__ m1, const float* __restrict__ v1) {
    int t = threadIdx.x;
    if (t < FEAT) {
        float inv0 = g0[t] / sqrtf(v0[t] + BNEPS);
        g_A0[t] = make_float4(w0[t * 3 + 0] * inv0,
                              w0[t * 3 + 1] * inv0,
                              w0[t * 3 + 2] * inv0,
                              (b0[t] - m0[t]) * inv0 + be0[t]);
        float inv1 = g1[t] / sqrtf(v1[t] + BNEPS);
        g_c1[t] = (b1[t] - m1[t]) * inv1 + be1[t];
    }
    for (int e = t; e < FEAT * 32; e += blockDim.x) {
        int c = e >> 5, l = e & 31;
        float invA = g1[l]      / sqrtf(v1[l]      + BNEPS);
        float invB = g1[l + 32] / sqrtf(v1[l + 32] + BNEPS);
        g_A1p[e] = make_float2(w1[l * FEAT + c] * invA,
                               w1[(l + 32) * FEAT + c] * invB);
    }
}

// ---------------- phase 1: brute-force KNN over an M-segment ----------------
// (R7 configuration — measured best.) Branchless bitmask filter (conservative
// surrogate, slack 1e-3 >> ~1e-5 rounding skew); drain walks set bits and
// recomputes the reference's exact fp32 arithmetic:
//   q2 = (qx*qx + qy*qy) + qz*qz ; o2 likewise (plain rn mul/add)
//   cross = fma(qz,oz, fma(qy,oy, rn(qx*ox)))
//   d2 = (q2 + o2) - (2*cross)
#define T1    128
#define TILE  1024
#define CHUNK 32

__global__ __launch_bounds__(T1, 8) void knn_kernel(const float* __restrict__ op,
                                                    const float* __restrict__ qp) {
    __shared__ float4 sh[TILE];           // (ox, oy, oz, -o2)  16 KB

    const int tid  = threadIdx.x;
    const int b    = blockIdx.y;
    const int segi = blockIdx.z;
    const int n    = blockIdx.x * T1 + tid;
    const float* opb = op + (size_t)b * 3 * MP;

    const float qx = qp[(size_t)b * 3 * NQ + n];
    const float qy = qp[(size_t)b * 3 * NQ + NQ + n];
    const float qz = qp[(size_t)b * 3 * NQ + 2 * NQ + n];
    const float q2 = __fadd_rn(__fadd_rn(__fmul_rn(qx, qx), __fmul_rn(qy, qy)),
                               __fmul_rn(qz, qz));
    const float tqx = qx + qx, tqy = qy + qy, tqz = qz + qz;

    float best[KNN];   // sorted ascending
    int   bidx[KNN];
#pragma unroll
    for (int i = 0; i < KNN; i++) { best[i] = 3.4e38f; bidx[i] = 0; }
    float c0 = -3.4e38f;   // pass iff surrogate t > c0 (saturated while sentinel)

    const int base0 = segi * SEG;
    for (int base = base0; base < base0 + SEG; base += TILE) {
        __syncthreads();
        for (int i = tid; i < TILE; i += T1) {
            float ox = opb[base + i];
            float oy = opb[MP + base + i];
            float oz = opb[2 * MP + base + i];
            float o2 = __fadd_rn(__fadd_rn(__fmul_rn(ox, ox), __fmul_rn(oy, oy)),
                                 __fmul_rn(oz, oz));
            sh[i] = make_float4(ox, oy, oz, -o2);
        }
        __syncthreads();

        for (int cs = 0; cs < TILE; cs += CHUNK) {
            unsigned mask = 0u;
            // ---- branchless bitmask filter: ~6 slots per candidate ----
#pragma unroll
            for (int jj = 0; jj < CHUNK; jj++) {
                float4 o = sh[cs + jj];
                float t = fmaf(tqz, o.z, fmaf(tqy, o.y, fmaf(tqx, o.x, o.w)));
                if (t > c0) mask |= (1u << jj);   // ISETP + predicated LOP3
            }
            // ---- drain set bits (divergent, only real candidates) ----
            while (mask) {
                int jj = __ffs(mask) - 1;
                mask &= mask - 1;
                int j = cs + jj;
                float4 o = sh[j];
                float o2 = -o.w;
                float cross = fmaf(qz, o.z, fmaf(qy, o.y, __fmul_rn(qx, o.x)));
                float d2 = __fsub_rn(__fadd_rn(q2, o2), __fmul_rn(2.0f, cross));
                if (d2 < best[KNN - 1]) {
                    int m = base + j;
                    bool pr[KNN];
#pragma unroll
                    for (int i = 0; i < KNN; i++) pr[i] = best[i] > d2;
#pragma unroll
                    for (int i = KNN - 1; i >= 1; i--)
                        if (pr[i - 1]) { best[i] = best[i - 1]; bidx[i] = bidx[i - 1]; }
#pragma unroll
                    for (int i = 0; i < KNN; i++)
                        if (pr[i] && (i == 0 || !pr[i - 1])) { best[i] = d2; bidx[i] = m; }
                    c0 = __fsub_rn(__fsub_rn(q2, best[KNN - 1]), 1e-3f);
                }
            }
        }
    }

    float* dk = g_kd + ((size_t)b * NQ + n) * 64 + segi * KNN;
    int*   di = g_ki + ((size_t)b * NQ + n) * 64 + segi * KNN;
#pragma unroll
    for (int i = 0; i < KNN; i++) { dk[i] = best[i]; di[i] = bidx[i]; }
}

// ---------------- phase 2: merge 4 lists + fused MLP + gather + blend ----------------
// 512 threads = 16 warps, one query per warp.
#define QPB 16

// bitonic merge of a 32-lane bitonic sequence, ascending, ties by lower index
__device__ __forceinline__ void bitonic32(float& d, int& id, int lane) {
#pragma unroll
    for (int j = 16; j >= 1; j >>= 1) {
        float od = __shfl_xor_sync(0xffffffffu, d, j);
        int   oi = __shfl_xor_sync(0xffffffffu, id, j);
        bool mineSmall = (d < od) || (d == od && id < oi);
        bool lower = !(lane & j);
        if (lower != mineSmall) { d = od; id = oi; }
    }
}

// combine two sorted-32s (top16 in lanes 0..15 of each) into one sorted-32
__device__ __forceinline__ void mergeTop(float& dA, int& iA, float dB, int iB, int lane) {
    float dBr = __shfl_sync(0xffffffffu, dB, 31 - lane);
    int   iBr = __shfl_sync(0xffffffffu, iB, 31 - lane);
    if (lane >= 16) { dA = dBr; iA = iBr; }
    bitonic32(dA, iA, lane);
}

__global__ __launch_bounds__(512) void feat_kernel(const float* __restrict__ op,
                                                   const float* __restrict__ qp,
                                                   const float* __restrict__ lf,
                                                   const float* __restrict__ w2,
                                                   const float* __restrict__ b2,
                                                   float* __restrict__ out) {
    __shared__ float2 shA1[FEAT * 32];       // 16 KB
    __shared__ float4 shF0[QPB][FEAT];       // 16 KB
    __shared__ float  shOut[FEAT][QPB + 2];  // padded stride

    const int tid  = threadIdx.x;
    const int warp = tid >> 5;
    const int lane = tid & 31;

    for (int i = tid; i < FEAT * 32; i += 512) shA1[i] = g_A1p[i];
    __syncthreads();

    const int b = blockIdx.y;
    const int n = blockIdx.x * QPB + warp;

    // ---- merge four sorted 16-lists into global top-16 ----
    const float* dk = g_kd + ((size_t)b * NQ + n) * 64;
    const int*   di = g_ki + ((size_t)b * NQ + n) * 64;

    int sA = (lane < 16) ? lane : (16 + 31 - lane);         // lists 0,1 -> bitonic
    float dA = dk[sA];  int iA = di[sA];
    bitonic32(dA, iA, lane);                                // sorted 32; top16 in lanes 0..15

    int sB = (lane < 16) ? (32 + lane) : (48 + 31 - lane);  // lists 2,3 -> bitonic
    float dB = dk[sB];  int iB = di[sB];
    bitonic32(dB, iB, lane);

    mergeTop(dA, iA, dB, iB, lane);
    // lanes 0..15 hold the global top-16 ascending (ties: lower index first)
    const int myidx = iA;

    const float qx = qp[(size_t)b * 3 * NQ + n];
    const float qy = qp[(size_t)b * 3 * NQ + NQ + n];
    const float qz = qp[(size_t)b * 3 * NQ + 2 * NQ + n];

    float rx = 0.f, ry = 0.f, rz = 0.f;
    if (lane < KNN) {
        const float* opb = op + (size_t)b * 3 * MP;
        rx = opb[myidx] - qx;
        ry = opb[MP + myidx] - qy;
        rz = opb[2 * MP + myidx] - qz;
    }

    const int f0 = lane, f1 = lane + 32;
    const float4 a0 = g_A0[f0];
    const float4 a1 = g_A0[f1];

    float gmax0 = 0.f, gmax1 = 0.f;   // relu outputs >= 0
#pragma unroll
    for (int k = 0; k < KNN; k++) {
        float ox = __shfl_sync(0xffffffffu, rx, k);
        float oy = __shfl_sync(0xffffffffu, ry, k);
        float oz = __shfl_sync(0xffffffffu, rz, k);
        float v0 = fmaxf(0.f, fmaf(a0.x, ox, fmaf(a0.y, oy, fmaf(a0.z, oz, a0.w))));
        float v1 = fmaxf(0.f, fmaf(a1.x, ox, fmaf(a1.y, oy, fmaf(a1.z, oz, a1.w))));
        gmax0 = fmaxf(gmax0, v0);
        gmax1 = fmaxf(gmax1, v1);
        if (k < K4) {
            ((float*)&shF0[warp][f0])[k] = v0;
            ((float*)&shF0[warp][f1])[k] = v1;
        }
    }
    __syncwarp();

    float sg = fmaf(w2[FEAT + f0], gmax0, w2[FEAT + f1] * gmax1);

    float a00 = 0.f, a01 = 0.f, a02 = 0.f, a03 = 0.f;
    float a10 = 0.f, a11 = 0.f, a12 = 0.f, a13 = 0.f;
#pragma unroll 8
    for (int c = 0; c < FEAT; c++) {
        float4 x = shF0[warp][c];            // broadcast LDS.128
        float2 a = shA1[c * 32 + lane];      // conflict-free LDS.64
        a00 = fmaf(a.x, x.x, a00); a01 = fmaf(a.x, x.y, a01);
        a02 = fmaf(a.x, x.z, a02); a03 = fmaf(a.x, x.w, a03);
        a10 = fmaf(a.y, x.x, a10); a11 = fmaf(a.y, x.y, a11);
        a12 = fmaf(a.y, x.z, a12); a13 = fmaf(a.y, x.w, a13);
    }
    const float c1a = g_c1[f0], c1b = g_c1[f1];
    float rf0[K4] = { fmaxf(0.f, a00 + c1a), fmaxf(0.f, a01 + c1a),
                      fmaxf(0.f, a02 + c1a), fmaxf(0.f, a03 + c1a) };
    float rf1[K4] = { fmaxf(0.f, a10 + c1b), fmaxf(0.f, a11 + c1b),
                      fmaxf(0.f, a12 + c1b), fmaxf(0.f, a13 + c1b) };

    const float w2a0 = w2[f0], w2a1 = w2[f1];
    float s0 = fmaf(w2a0, rf0[0], w2a1 * rf1[0]);
    float s1 = fmaf(w2a0, rf0[1], w2a1 * rf1[1]);
    float s2 = fmaf(w2a0, rf0[2], w2a1 * rf1[2]);
    float s3 = fmaf(w2a0, rf0[3], w2a1 * rf1[3]);
#pragma unroll
    for (int off = 16; off; off >>= 1) {
        s0 += __shfl_xor_sync(0xffffffffu, s0, off);
        s1 += __shfl_xor_sync(0xffffffffu, s1, off);
        s2 += __shfl_xor_sync(0xffffffffu, s2, off);
        s3 += __shfl_xor_sync(0xffffffffu, s3, off);
        sg += __shfl_xor_sync(0xffffffffu, sg, off);
    }
    const float bb2 = b2[0];
    float wgt[K4];
    wgt[0] = 1.f / (1.f + expf(-(s0 + sg + bb2)));
    wgt[1] = 1.f / (1.f + expf(-(s1 + sg + bb2)));
    wgt[2] = 1.f / (1.f + expf(-(s2 + sg + bb2)));
    wgt[3] = 1.f / (1.f + expf(-(s3 + sg + bb2)));

    const float* lfb = lf + (size_t)b * FEAT * MP;
    float o0 = 0.f, o1 = 0.f;
#pragma unroll
    for (int j = 0; j < K4; j++) {
        int idj = __shfl_sync(0xffffffffu, myidx, j);
        float p0 = lfb[(size_t)f0 * MP + idj];
        float p1 = lfb[(size_t)f1 * MP + idj];
        o0 += rf0[j] + wgt[j] * (p0 - rf0[j]);
        o1 += rf1[j] + wgt[j] * (p1 - rf1[j]);
    }
    shOut[f0][warp] = o0;
    shOut[f1][warp] = o1;
    __syncthreads();

    // coalesced write: thread t -> feature t/8, n-offset (t%8)*2
    int f = tid >> 3, seg = tid & 7;
    int nbase = blockIdx.x * QPB;
    float2 v = make_float2(shOut[f][seg * 2], shOut[f][seg * 2 + 1]);
    *(float2*)&out[((size_t)b * FEAT + f) * NQ + nbase + seg * 2] = v;
}

// ---------------- launch ----------------
extern "C" void kernel_launch(void* const* d_in, const int* in_sizes, int n_in,
                              void* d_out, int out_size) {
    const float* original_pts = (const float*)d_in[0];
    const float* query_pts    = (const float*)d_in[1];
    const float* local_feat   = (const float*)d_in[2];
    const float* w0  = (const float*)d_in[3];
    const float* b0  = (const float*)d_in[4];
    const float* g0  = (const float*)d_in[5];
    const float* be0 = (const float*)d_in[6];
    const float* m0  = (const float*)d_in[7];
    const float* v0  = (const float*)d_in[8];
    const float* w1  = (const float*)d_in[9];
    const float* b1  = (const float*)d_in[10];
    const float* g1  = (const float*)d_in[11];
    const float* be1 = (const float*)d_in[12];
    const float* m1  = (const float*)d_in[13];
    const float* v1  = (const float*)d_in[14];
    const float* w2  = (const float*)d_in[15];
    const float* b2  = (const float*)d_in[16];
    float* out = (float*)d_out;

    // knn first so the profiler capture lands on the hot kernel.
    dim3 g1d(NQ / T1, BB, NSPLIT);
    knn_kernel<<<g1d, T1>>>(original_pts, query_pts);

    prep_kernel<<<1, 256>>>(w0, b0, g0, be0, m0, v0, w1, b1, g1, be1, m1, v1);

    dim3 g2d(NQ / QPB, BB);
    feat_kernel<<<g2d, 512>>>(original_pts, query_pts, local_feat, w2, b2, out);
}